// round 7
// baseline (speedup 1.0000x reference)
#include <cuda_runtime.h>
#include <cuda_bf16.h>
#include <math.h>

// ---------------- model constants ----------------
#define Vv 50257
#define VP 50304            // padded vocab (multiple of 128)
#define Dd 768
#define Hh 12
#define HD 64
#define Tt 1024
#define Ll 6
#define Bb 4
#define BT (Bb*Tt)          // 4096
#define FF (4*Dd)           // 3072

#define BM 128
#define BN 128
#define BKK 16
#define APAD 68             // attention smem row stride (floats)

// ---------------- scratch (static device arrays; no allocation) ----------------
__device__ float g_x   [BT*Dd];
__device__ float g_x2  [BT*Dd];
__device__ float g_q   [BT*Dd];
__device__ float g_k   [BT*Dd];
__device__ float g_v   [BT*Dd];
__device__ float g_y   [BT*Dd];
__device__ float g_ff1 [BT*FF];
__device__ float g_rl  [BT];
__device__ float g_wpad[(size_t)Dd*VP];   // padded, pre-tf32 head weights

__device__ __forceinline__ float to_tf32(float x) {
    float y;
    asm("cvt.rna.tf32.f32 %0, %1;" : "=f"(y) : "f"(x));
    return y;
}

// ---------------- embedding ----------------
__global__ void embed_kernel(const int* __restrict__ idx,
                             const float* __restrict__ tok,
                             const float* __restrict__ pos,
                             float* __restrict__ x) {
    int r = blockIdx.x;
    int t = r & (Tt - 1);
    int token = idx[r];
    const float* tr = tok + (size_t)token * Dd;
    const float* pr = pos + (size_t)t * Dd;
    float* xr = x + (size_t)r * Dd;
    for (int c = threadIdx.x; c < Dd; c += blockDim.x)
        xr[c] = tr[c] + pr[c];
}

// ---------------- pad + pre-convert head weights ----------------
__global__ void padw_kernel(const float* __restrict__ w, float* __restrict__ wp) {
    int kk = blockIdx.x;             // 0..767
    const float* src = w + (size_t)kk * Vv;
    float* dst = wp + (size_t)kk * VP;
    for (int n = threadIdx.x; n < VP; n += blockDim.x)
        dst[n] = (n < Vv) ? to_tf32(src[n]) : 0.f;
}

// ---------------- TF32 tensor-core GEMM core (double-buffered) ----------------
// BM=128, BN=128, BK=16. 256 threads = 8 warps (2M x 4N), warp tile 64x32,
// mma.m16n8k8.tf32. Double-buffered smem: LDG(next) -> compute(cur) ->
// STS(next) -> ONE sync per k-tile.
template<int EPI>
__device__ __forceinline__ void gemm_core(
    const float* __restrict__ A, const float* __restrict__ Bm,
    const float* __restrict__ bias, float* __restrict__ C,
    int N, int K, int Bstride, int row0, int col0)
{
    __shared__ float As[2][BKK][BM + 4];   // ~17 KB
    __shared__ float Bs[2][BKK][BN + 4];   // ~17 KB

    int t    = threadIdx.x;
    int wid  = t >> 5;
    int lane = t & 31;
    int g    = lane >> 2;
    int tig  = lane & 3;
    int m0w  = (wid & 1) * 64;
    int n0w  = (wid >> 1) * 32;

    const bool vec_ok = ((col0 + BN) <= Bstride) && ((Bstride & 3) == 0);

    // per-thread load coordinates (R3 mapping)
    const int arow0 = (t + 0)   >> 2, aseg0 = ((t + 0)   & 3) * 4;
    const int arow1 = (t + 256) >> 2, aseg1 = ((t + 256) & 3) * 4;
    const int bkr0  = (t + 0)   >> 5, bcs0  = ((t + 0)   & 31) * 4;
    const int bkr1  = (t + 256) >> 5, bcs1  = ((t + 256) & 31) * 4;

    float4 aS0, aS1;       // A staging
    float4 bS0, bS1;       // B staging (vec)
    float  bSs[8];         // B staging (scalar)

    float acc[4][4][4];
#pragma unroll
    for (int im = 0; im < 4; im++)
#pragma unroll
        for (int in = 0; in < 4; in++)
#pragma unroll
            for (int c = 0; c < 4; c++) acc[im][in][c] = 0.f;

    auto loadAB = [&](int k0) {
        aS0 = *(const float4*)(A + (size_t)(row0 + arow0) * K + k0 + aseg0);
        aS1 = *(const float4*)(A + (size_t)(row0 + arow1) * K + k0 + aseg1);
        if (vec_ok) {
            bS0 = *(const float4*)(Bm + (size_t)(k0 + bkr0) * Bstride + col0 + bcs0);
            bS1 = *(const float4*)(Bm + (size_t)(k0 + bkr1) * Bstride + col0 + bcs1);
        } else {
#pragma unroll
            for (int i = 0; i < 8; i++) {
                int e = t + i * 256;
                int kr = e >> 7, c = e & 127;
                int col = col0 + c;
                bSs[i] = (col < Bstride) ? Bm[(size_t)(k0 + kr) * Bstride + col] : 0.f;
            }
        }
    };
    auto storeAB = [&](int buf) {
        As[buf][aseg0 + 0][arow0] = to_tf32(aS0.x);
        As[buf][aseg0 + 1][arow0] = to_tf32(aS0.y);
        As[buf][aseg0 + 2][arow0] = to_tf32(aS0.z);
        As[buf][aseg0 + 3][arow0] = to_tf32(aS0.w);
        As[buf][aseg1 + 0][arow1] = to_tf32(aS1.x);
        As[buf][aseg1 + 1][arow1] = to_tf32(aS1.y);
        As[buf][aseg1 + 2][arow1] = to_tf32(aS1.z);
        As[buf][aseg1 + 3][arow1] = to_tf32(aS1.w);
        if (vec_ok) {
            Bs[buf][bkr0][bcs0 + 0] = to_tf32(bS0.x);
            Bs[buf][bkr0][bcs0 + 1] = to_tf32(bS0.y);
            Bs[buf][bkr0][bcs0 + 2] = to_tf32(bS0.z);
            Bs[buf][bkr0][bcs0 + 3] = to_tf32(bS0.w);
            Bs[buf][bkr1][bcs1 + 0] = to_tf32(bS1.x);
            Bs[buf][bkr1][bcs1 + 1] = to_tf32(bS1.y);
            Bs[buf][bkr1][bcs1 + 2] = to_tf32(bS1.z);
            Bs[buf][bkr1][bcs1 + 3] = to_tf32(bS1.w);
        } else {
#pragma unroll
            for (int i = 0; i < 8; i++) {
                int e = t + i * 256;
                int kr = e >> 7, c = e & 127;
                Bs[buf][kr][c] = to_tf32(bSs[i]);
            }
        }
    };
    auto compute = [&](int buf) {
#pragma unroll
        for (int ks = 0; ks < BKK; ks += 8) {
            unsigned af[4][4], bf[4][2];
#pragma unroll
            for (int im = 0; im < 4; im++) {
                int m = m0w + im * 16 + g;
                af[im][0] = __float_as_uint(As[buf][ks + tig    ][m    ]);
                af[im][1] = __float_as_uint(As[buf][ks + tig    ][m + 8]);
                af[im][2] = __float_as_uint(As[buf][ks + tig + 4][m    ]);
                af[im][3] = __float_as_uint(As[buf][ks + tig + 4][m + 8]);
            }
#pragma unroll
            for (int in = 0; in < 4; in++) {
                int n = n0w + in * 8 + g;
                bf[in][0] = __float_as_uint(Bs[buf][ks + tig    ][n]);
                bf[in][1] = __float_as_uint(Bs[buf][ks + tig + 4][n]);
            }
#pragma unroll
            for (int im = 0; im < 4; im++)
#pragma unroll
                for (int in = 0; in < 4; in++) {
                    asm volatile(
                        "mma.sync.aligned.m16n8k8.row.col.f32.tf32.tf32.f32 "
                        "{%0,%1,%2,%3},{%4,%5,%6,%7},{%8,%9},{%0,%1,%2,%3};"
                        : "+f"(acc[im][in][0]), "+f"(acc[im][in][1]),
                          "+f"(acc[im][in][2]), "+f"(acc[im][in][3])
                        : "r"(af[im][0]), "r"(af[im][1]), "r"(af[im][2]), "r"(af[im][3]),
                          "r"(bf[in][0]), "r"(bf[in][1]));
                }
        }
    };

    // ---- double-buffered mainloop: one sync per k-tile ----
    loadAB(0);
    storeAB(0);
    __syncthreads();
    int cur = 0;
    for (int k0 = BKK; k0 < K; k0 += BKK) {
        loadAB(k0);            // LDGs in flight during compute
        compute(cur);
        storeAB(cur ^ 1);
        __syncthreads();
        cur ^= 1;
    }
    compute(cur);

    // ---- epilogue ----
#pragma unroll
    for (int im = 0; im < 4; im++) {
        int r_lo = row0 + m0w + im * 16 + g;
        int r_hi = r_lo + 8;
#pragma unroll
        for (int in = 0; in < 4; in++) {
            int c_lo = col0 + n0w + in * 8 + 2 * tig;
            int c_hi = c_lo + 1;
            float v0 = acc[im][in][0], v1 = acc[im][in][1];
            float v2 = acc[im][in][2], v3 = acc[im][in][3];
            if (EPI >= 1) {
                if (c_lo < N) { v0 += bias[c_lo]; v2 += bias[c_lo]; }
                if (c_hi < N) { v1 += bias[c_hi]; v3 += bias[c_hi]; }
            }
            if (EPI == 2) {
                v0 = fmaxf(v0, 0.f); v1 = fmaxf(v1, 0.f);
                v2 = fmaxf(v2, 0.f); v3 = fmaxf(v3, 0.f);
            }
            size_t blo = (size_t)r_lo * N;
            size_t bhi = (size_t)r_hi * N;
            if (c_lo < N) { C[blo + c_lo] = v0; C[bhi + c_lo] = v2; }
            if (c_hi < N) { C[blo + c_hi] = v1; C[bhi + c_hi] = v3; }
        }
    }
}

template<int EPI>
__global__ __launch_bounds__(256)
void tgemm_kernel(const float* __restrict__ A, const float* __restrict__ Bm,
                  const float* __restrict__ bias, float* __restrict__ C,
                  int N, int K, int Bstride) {
    gemm_core<EPI>(A, Bm, bias, C, N, K, Bstride,
                   blockIdx.y * BM, blockIdx.x * BN);
}

// fused QKV: grid (18, 32); blockIdx.x selects {Wq,Wk,Wv} x 6 col-tiles
__global__ __launch_bounds__(256)
void qkv_kernel(const float* __restrict__ x,
                const float* __restrict__ wq, const float* __restrict__ wk,
                const float* __restrict__ wv,
                float* __restrict__ q, float* __restrict__ k, float* __restrict__ v) {
    int ct  = blockIdx.x;          // 0..17
    int mat = ct / 6;
    int c   = ct % 6;
    const float* B = (mat == 0) ? wq : (mat == 1) ? wk : wv;
    float*       C = (mat == 0) ? q  : (mat == 1) ? k  : v;
    gemm_core<0>(x, B, nullptr, C, Dd, Dd, Dd, blockIdx.y * BM, c * BN);
}

// ---------------- causal flash attention (R5-verified) ----------------
#define ATTN_SMEM ((4*64*APAD + 3*64) * 4)
__global__ __launch_bounds__(256)
void attn_kernel(const float* __restrict__ q, const float* __restrict__ k,
                 const float* __restrict__ v, float* __restrict__ y) {
    extern __shared__ float asmem[];
    float* Qs   = asmem;
    float* Ks   = Qs + 64 * APAD;
    float* Vs   = Ks + 64 * APAD;
    float* Ss   = Vs + 64 * APAD;
    float* mrow = Ss + 64 * APAD;
    float* lrow = mrow + 64;
    float* cfac = lrow + 64;

    int t  = threadIdx.x;
    int q0 = blockIdx.x * 64;
    int h  = blockIdx.y;
    int b  = blockIdx.z;

    for (int i = t; i < 64 * 16; i += 256) {
        int r = i >> 4, c4 = i & 15;
        *(float4*)(Qs + r * APAD + c4 * 4) =
            *(const float4*)(q + ((size_t)(b * Tt + q0 + r)) * Dd + h * HD + c4 * 4);
    }
    if (t < 64) { mrow[t] = -1e30f; lrow[t] = 0.f; }

    int qg  = t >> 4;
    int qi0 = qg * 4;
    int kb  = t & 15;

    float acc[4][4];
#pragma unroll
    for (int i = 0; i < 4; i++)
#pragma unroll
        for (int dc = 0; dc < 4; dc++) acc[i][dc] = 0.f;

    int ntiles = blockIdx.x + 1;
    __syncthreads();

    for (int jt = 0; jt < ntiles; jt++) {
        int s0 = jt * 64;
        for (int i = t; i < 64 * 16; i += 256) {
            int r = i >> 4, c4 = i & 15;
            size_t gb = ((size_t)(b * Tt + s0 + r)) * Dd + h * HD + c4 * 4;
            *(float4*)(Ks + r * APAD + c4 * 4) = *(const float4*)(k + gb);
            *(float4*)(Vs + r * APAD + c4 * 4) = *(const float4*)(v + gb);
        }
        __syncthreads();

        float s[4][4];
#pragma unroll
        for (int i = 0; i < 4; i++)
#pragma unroll
            for (int jj = 0; jj < 4; jj++) s[i][jj] = 0.f;
#pragma unroll
        for (int c = 0; c < 16; c++) {
            float4 qv[4], kv[4];
#pragma unroll
            for (int i = 0; i < 4; i++)
                qv[i] = *(float4*)(Qs + (qi0 + i) * APAD + c * 4);
#pragma unroll
            for (int jj = 0; jj < 4; jj++)
                kv[jj] = *(float4*)(Ks + (kb + 16 * jj) * APAD + c * 4);
#pragma unroll
            for (int i = 0; i < 4; i++)
#pragma unroll
                for (int jj = 0; jj < 4; jj++)
                    s[i][jj] += qv[i].x * kv[jj].x + qv[i].y * kv[jj].y
                              + qv[i].z * kv[jj].z + qv[i].w * kv[jj].w;
        }
#pragma unroll
        for (int i = 0; i < 4; i++)
#pragma unroll
            for (int jj = 0; jj < 4; jj++) {
                int qi = qi0 + i, kj = kb + 16 * jj;
                float val = s[i][jj] * 0.125f;
                if (s0 + kj > q0 + qi) val = -1e30f;
                Ss[qi * APAD + kj] = val;
            }
        __syncthreads();

        if (t < 64) {
            float m = mrow[t], nm = m;
            float* srow = Ss + t * APAD;
#pragma unroll 8
            for (int kj = 0; kj < 64; kj++) nm = fmaxf(nm, srow[kj]);
            float corr = __expf(m - nm);
            float sum = 0.f;
#pragma unroll 8
            for (int kj = 0; kj < 64; kj++) {
                float p = __expf(srow[kj] - nm);
                srow[kj] = p;
                sum += p;
            }
            lrow[t] = lrow[t] * corr + sum;
            mrow[t] = nm;
            cfac[t] = corr;
        }
        __syncthreads();

#pragma unroll
        for (int i = 0; i < 4; i++) {
            float corr = cfac[qi0 + i];
#pragma unroll
            for (int dc = 0; dc < 4; dc++) acc[i][dc] *= corr;
        }
#pragma unroll
        for (int kc = 0; kc < 16; kc++) {
            float4 pv[4], vv[4];
#pragma unroll
            for (int i = 0; i < 4; i++)
                pv[i] = *(float4*)(Ss + (qi0 + i) * APAD + kc * 4);
#pragma unroll
            for (int jj = 0; jj < 4; jj++)
                vv[jj] = *(float4*)(Vs + (kc * 4 + jj) * APAD + kb * 4);
#pragma unroll
            for (int i = 0; i < 4; i++) {
                acc[i][0] += pv[i].x * vv[0].x + pv[i].y * vv[1].x + pv[i].z * vv[2].x + pv[i].w * vv[3].x;
                acc[i][1] += pv[i].x * vv[0].y + pv[i].y * vv[1].y + pv[i].z * vv[2].y + pv[i].w * vv[3].y;
                acc[i][2] += pv[i].x * vv[0].z + pv[i].y * vv[1].z + pv[i].z * vv[2].z + pv[i].w * vv[3].z;
                acc[i][3] += pv[i].x * vv[0].w + pv[i].y * vv[1].w + pv[i].z * vv[2].w + pv[i].w * vv[3].w;
            }
        }
        __syncthreads();
    }

#pragma unroll
    for (int i = 0; i < 4; i++) {
        float inv = 1.f / lrow[qi0 + i];
        float4 o;
        o.x = acc[i][0] * inv; o.y = acc[i][1] * inv;
        o.z = acc[i][2] * inv; o.w = acc[i][3] * inv;
        *(float4*)(y + ((size_t)(b * Tt + q0 + qi0 + i)) * Dd + h * HD + kb * 4) = o;
    }
}

// ---------------- residual + LayerNorm ----------------
__global__ __launch_bounds__(256)
void ln_res_kernel(const float* __restrict__ a, const float* __restrict__ b,
                   const float* __restrict__ g, const float* __restrict__ be,
                   float* __restrict__ out) {
    __shared__ float buf[Dd];
    __shared__ float red[256];
    int r = blockIdx.x;
    int t = threadIdx.x;
    const float* ar = a + (size_t)r * Dd;
    const float* br = b + (size_t)r * Dd;

    float s = 0.f;
    for (int c = t; c < Dd; c += 256) {
        float vv = ar[c] + br[c];
        buf[c] = vv;
        s += vv;
    }
    red[t] = s; __syncthreads();
    for (int o = 128; o > 0; o >>= 1) { if (t < o) red[t] += red[t + o]; __syncthreads(); }
    float mu = red[0] / (float)Dd;
    __syncthreads();

    float s2 = 0.f;
    for (int c = t; c < Dd; c += 256) {
        float d = buf[c] - mu;
        s2 += d * d;
    }
    red[t] = s2; __syncthreads();
    for (int o = 128; o > 0; o >>= 1) { if (t < o) red[t] += red[t + o]; __syncthreads(); }
    float rstd = rsqrtf(red[0] / (float)Dd + 1e-5f);

    float* orr = out + (size_t)r * Dd;
    for (int c = t; c < Dd; c += 256)
        orr[c] = (buf[c] - mu) * rstd * g[c] + be[c];
}

// ---------------- per-row cross-entropy ----------------
__global__ __launch_bounds__(256)
void rowloss_kernel(const float* __restrict__ logits, const int* __restrict__ tgt,
                    float* __restrict__ rl) {
    __shared__ float sm[256], sl[256];
    int r = blockIdx.x;
    int t = threadIdx.x;
    const float* lg = logits + (size_t)r * Vv;

    float m = -1e30f, l = 0.f;
    for (int c = t; c < Vv; c += 256) {
        float x = lg[c];
        if (x > m) { l = l * __expf(m - x) + 1.f; m = x; }
        else       { l += __expf(x - m); }
    }
    sm[t] = m; sl[t] = l; __syncthreads();
    for (int o = 128; o > 0; o >>= 1) {
        if (t < o) {
            float m1 = sm[t], m2 = sm[t + o];
            float M = fmaxf(m1, m2);
            sl[t] = sl[t] * __expf(m1 - M) + sl[t + o] * __expf(m2 - M);
            sm[t] = M;
        }
        __syncthreads();
    }
    if (t == 0)
        rl[r] = (sm[0] + logf(sl[0])) - lg[tgt[r]];
}

__global__ __launch_bounds__(256)
void meanloss_kernel(const float* __restrict__ rl, float* __restrict__ out) {
    __shared__ float red[256];
    int t = threadIdx.x;
    float s = 0.f;
    for (int i = t; i < BT; i += 256) s += rl[i];
    red[t] = s; __syncthreads();
    for (int o = 128; o > 0; o >>= 1) { if (t < o) red[t] += red[t + o]; __syncthreads(); }
    if (t == 0) out[0] = red[0] / (float)BT;
}

// ---------------- launch ----------------
extern "C" void kernel_launch(void* const* d_in, const int* in_sizes, int n_in,
                              void* d_out, int out_size) {
    const int*   idx    = (const int*)  d_in[0];
    const int*   tgt    = (const int*)  d_in[1];
    const float* tok    = (const float*)d_in[2];
    const float* pos    = (const float*)d_in[3];
    const float* Wq     = (const float*)d_in[4];
    const float* Wk     = (const float*)d_in[5];
    const float* Wv     = (const float*)d_in[6];
    const float* ln1g   = (const float*)d_in[7];
    const float* ln1b   = (const float*)d_in[8];
    const float* W1     = (const float*)d_in[9];
    const float* b1     = (const float*)d_in[10];
    const float* W2     = (const float*)d_in[11];
    const float* b2     = (const float*)d_in[12];
    const float* ln2g   = (const float*)d_in[13];
    const float* ln2b   = (const float*)d_in[14];
    const float* headw  = (const float*)d_in[15];
    const float* headb  = (const float*)d_in[16];
    float* out = (float*)d_out;

    float *x, *x2, *q, *k, *v, *y, *ff1, *rl, *wpad;
    cudaGetSymbolAddress((void**)&x,    g_x);
    cudaGetSymbolAddress((void**)&x2,   g_x2);
    cudaGetSymbolAddress((void**)&q,    g_q);
    cudaGetSymbolAddress((void**)&k,    g_k);
    cudaGetSymbolAddress((void**)&v,    g_v);
    cudaGetSymbolAddress((void**)&y,    g_y);
    cudaGetSymbolAddress((void**)&ff1,  g_ff1);
    cudaGetSymbolAddress((void**)&rl,   g_rl);
    cudaGetSymbolAddress((void**)&wpad, g_wpad);

    cudaFuncSetAttribute(attn_kernel,
                         cudaFuncAttributeMaxDynamicSharedMemorySize, ATTN_SMEM);

    embed_kernel<<<BT, 256>>>(idx, tok, pos, x);
    padw_kernel<<<Dd, 256>>>(headw, wpad);

    dim3 gQKV(18, BT / 128);
    dim3 gD(Dd / 128, BT / 128);             // 6 x 32
    dim3 gF(FF / 128, BT / 128);             // 24 x 32
    dim3 gV(VP / 128, BT / 128);             // 393 x 32

    for (int l = 0; l < Ll; l++) {
        const float* wq = Wq + (size_t)l * Dd * Dd;
        const float* wk = Wk + (size_t)l * Dd * Dd;
        const float* wv = Wv + (size_t)l * Dd * Dd;
        const float* w1 = W1 + (size_t)l * Dd * FF;
        const float* w2 = W2 + (size_t)l * FF * Dd;

        qkv_kernel<<<gQKV, 256>>>(x, wq, wk, wv, q, k, v);

        attn_kernel<<<dim3(Tt / 64, Hh, Bb), 256, ATTN_SMEM>>>(q, k, v, y);

        ln_res_kernel<<<BT, 256>>>(y, x, ln1g + l * Dd, ln1b + l * Dd, x2);

        tgemm_kernel<2><<<gF, 256>>>(x2, w1, b1 + (size_t)l * FF, ff1, FF, Dd, FF);
        tgemm_kernel<1><<<gD, 256>>>(ff1, w2, b2 + (size_t)l * Dd, y, Dd, FF, Dd);

        ln_res_kernel<<<BT, 256>>>(y, x2, ln2g + l * Dd, ln2b + l * Dd, x);
    }

    // head: padded, pre-converted B with stride VP; stores guarded to N=Vv
    tgemm_kernel<1><<<gV, 256>>>(x, wpad, headb, out, Vv, Dd, VP);

    rowloss_kernel<<<BT, 256>>>(out, tgt, rl);
    meanloss_kernel<<<1, 256>>>(rl, out + (size_t)BT * Vv);
}

// round 8
// speedup vs baseline: 1.5337x; 1.5337x over previous
#include <cuda_runtime.h>
#include <cuda_bf16.h>
#include <math.h>

// ---------------- model constants ----------------
#define Vv 50257
#define VP 50304            // padded vocab (multiple of 128)
#define Dd 768
#define Hh 12
#define HD 64
#define Tt 1024
#define Ll 6
#define Bb 4
#define BT (Bb*Tt)          // 4096
#define FF (4*Dd)           // 3072

#define BM 128
#define BN 128
#define BKK 16
#define ATP 68              // attention smem row stride (floats)

// ---------------- scratch (static device arrays; no allocation) ----------------
__device__ float g_x   [BT*Dd];
__device__ float g_x2  [BT*Dd];
__device__ float g_q   [BT*Dd];
__device__ float g_k   [BT*Dd];
__device__ float g_v   [BT*Dd];
__device__ float g_y   [BT*Dd];
__device__ float g_ff1 [BT*FF];
__device__ float g_rl  [BT];
__device__ float g_wpad[(size_t)Dd*VP];   // padded, pre-tf32 head weights

__device__ __forceinline__ float to_tf32(float x) {
    float y;
    asm("cvt.rna.tf32.f32 %0, %1;" : "=f"(y) : "f"(x));
    return y;
}

// ---------------- embedding ----------------
__global__ void embed_kernel(const int* __restrict__ idx,
                             const float* __restrict__ tok,
                             const float* __restrict__ pos,
                             float* __restrict__ x) {
    int r = blockIdx.x;
    int t = r & (Tt - 1);
    int token = idx[r];
    const float* tr = tok + (size_t)token * Dd;
    const float* pr = pos + (size_t)t * Dd;
    float* xr = x + (size_t)r * Dd;
    for (int c = threadIdx.x; c < Dd; c += blockDim.x)
        xr[c] = tr[c] + pr[c];
}

// ---------------- pad + pre-convert head weights ----------------
__global__ void padw_kernel(const float* __restrict__ w, float* __restrict__ wp) {
    int kk = blockIdx.x;             // 0..767
    const float* src = w + (size_t)kk * Vv;
    float* dst = wp + (size_t)kk * VP;
    for (int n = threadIdx.x; n < VP; n += blockDim.x)
        dst[n] = (n < Vv) ? to_tf32(src[n]) : 0.f;
}

// ---------------- TF32 tensor-core GEMM core (R3-verified, FROZEN) ----------------
template<int EPI>
__device__ __forceinline__ void gemm_core(
    const float* __restrict__ A, const float* __restrict__ Bm,
    const float* __restrict__ bias, float* __restrict__ C,
    int N, int K, int Bstride, int row0, int col0)
{
    __shared__ float As[BKK][BM + 4];   // As[k][m]
    __shared__ float Bs[BKK][BN + 4];   // Bs[k][n]

    int t    = threadIdx.x;
    int wid  = t >> 5;
    int lane = t & 31;
    int g    = lane >> 2;
    int tig  = lane & 3;
    int m0w  = (wid & 1) * 64;
    int n0w  = (wid >> 1) * 32;

    const bool vec_ok = ((col0 + BN) <= Bstride) && ((Bstride & 3) == 0);

    float acc[4][4][4];
#pragma unroll
    for (int im = 0; im < 4; im++)
#pragma unroll
        for (int in = 0; in < 4; in++)
#pragma unroll
            for (int c = 0; c < 4; c++) acc[im][in][c] = 0.f;

    for (int k0 = 0; k0 < K; k0 += BKK) {
#pragma unroll
        for (int i = 0; i < 2; i++) {
            int idx = t + i * 256;
            int row = idx >> 2;
            int seg = (idx & 3) * 4;
            float4 a4 = *(const float4*)(A + (size_t)(row0 + row) * K + k0 + seg);
            As[seg + 0][row] = to_tf32(a4.x);
            As[seg + 1][row] = to_tf32(a4.y);
            As[seg + 2][row] = to_tf32(a4.z);
            As[seg + 3][row] = to_tf32(a4.w);
        }
        if (vec_ok) {
#pragma unroll
            for (int i = 0; i < 2; i++) {
                int idx = t + i * 256;
                int kr  = idx >> 5;
                int cs  = (idx & 31) * 4;
                float4 b4 = *(const float4*)(Bm + (size_t)(k0 + kr) * Bstride + col0 + cs);
                Bs[kr][cs + 0] = to_tf32(b4.x);
                Bs[kr][cs + 1] = to_tf32(b4.y);
                Bs[kr][cs + 2] = to_tf32(b4.z);
                Bs[kr][cs + 3] = to_tf32(b4.w);
            }
        } else {
#pragma unroll
            for (int i = 0; i < 8; i++) {
                int e = t + i * 256;
                int kr = e >> 7;
                int c  = e & 127;
                int col = col0 + c;
                Bs[kr][c] = (col < Bstride) ? to_tf32(Bm[(size_t)(k0 + kr) * Bstride + col]) : 0.f;
            }
        }
        __syncthreads();

#pragma unroll
        for (int ks = 0; ks < BKK; ks += 8) {
            unsigned af[4][4], bf[4][2];
#pragma unroll
            for (int im = 0; im < 4; im++) {
                int m = m0w + im * 16 + g;
                af[im][0] = __float_as_uint(As[ks + tig    ][m    ]);
                af[im][1] = __float_as_uint(As[ks + tig    ][m + 8]);
                af[im][2] = __float_as_uint(As[ks + tig + 4][m    ]);
                af[im][3] = __float_as_uint(As[ks + tig + 4][m + 8]);
            }
#pragma unroll
            for (int in = 0; in < 4; in++) {
                int n = n0w + in * 8 + g;
                bf[in][0] = __float_as_uint(Bs[ks + tig    ][n]);
                bf[in][1] = __float_as_uint(Bs[ks + tig + 4][n]);
            }
#pragma unroll
            for (int im = 0; im < 4; im++)
#pragma unroll
                for (int in = 0; in < 4; in++) {
                    asm volatile(
                        "mma.sync.aligned.m16n8k8.row.col.f32.tf32.tf32.f32 "
                        "{%0,%1,%2,%3},{%4,%5,%6,%7},{%8,%9},{%0,%1,%2,%3};"
                        : "+f"(acc[im][in][0]), "+f"(acc[im][in][1]),
                          "+f"(acc[im][in][2]), "+f"(acc[im][in][3])
                        : "r"(af[im][0]), "r"(af[im][1]), "r"(af[im][2]), "r"(af[im][3]),
                          "r"(bf[in][0]), "r"(bf[in][1]));
                }
        }
        __syncthreads();
    }

#pragma unroll
    for (int im = 0; im < 4; im++) {
        int r_lo = row0 + m0w + im * 16 + g;
        int r_hi = r_lo + 8;
#pragma unroll
        for (int in = 0; in < 4; in++) {
            int c_lo = col0 + n0w + in * 8 + 2 * tig;
            int c_hi = c_lo + 1;
            float v0 = acc[im][in][0], v1 = acc[im][in][1];
            float v2 = acc[im][in][2], v3 = acc[im][in][3];
            if (EPI >= 1) {
                if (c_lo < N) { v0 += bias[c_lo]; v2 += bias[c_lo]; }
                if (c_hi < N) { v1 += bias[c_hi]; v3 += bias[c_hi]; }
            }
            if (EPI == 2) {
                v0 = fmaxf(v0, 0.f); v1 = fmaxf(v1, 0.f);
                v2 = fmaxf(v2, 0.f); v3 = fmaxf(v3, 0.f);
            }
            size_t blo = (size_t)r_lo * N;
            size_t bhi = (size_t)r_hi * N;
            if (c_lo < N) { C[blo + c_lo] = v0; C[bhi + c_lo] = v2; }
            if (c_hi < N) { C[blo + c_hi] = v1; C[bhi + c_hi] = v3; }
        }
    }
}

template<int EPI>
__global__ __launch_bounds__(256)
void tgemm_kernel(const float* __restrict__ A, const float* __restrict__ Bm,
                  const float* __restrict__ bias, float* __restrict__ C,
                  int N, int K, int Bstride) {
    gemm_core<EPI>(A, Bm, bias, C, N, K, Bstride,
                   blockIdx.y * BM, blockIdx.x * BN);
}

__global__ __launch_bounds__(256)
void qkv_kernel(const float* __restrict__ x,
                const float* __restrict__ wq, const float* __restrict__ wk,
                const float* __restrict__ wv,
                float* __restrict__ q, float* __restrict__ k, float* __restrict__ v) {
    int ct  = blockIdx.x;
    int mat = ct / 6;
    int c   = ct % 6;
    const float* B = (mat == 0) ? wq : (mat == 1) ? wk : wv;
    float*       C = (mat == 0) ? q  : (mat == 1) ? k  : v;
    gemm_core<0>(x, B, nullptr, C, Dd, Dd, Dd, blockIdx.y * BM, c * BN);
}

// ---------------- tensor-core causal flash attention ----------------
// grid (T/64, H, B), 256 threads = 8 warps: 4 M-chunks (16 rows) x 2 N-chunks (32 cols).
// S = Q K^T and O = P V both via mma.m16n8k8.tf32 (same fragment layouts as gemm_core).
#define ATTN_SMEM ((4*64*ATP + 64*3 + 2*64*2) * 4)
__global__ __launch_bounds__(256)
void attn_kernel(const float* __restrict__ q, const float* __restrict__ k,
                 const float* __restrict__ v, float* __restrict__ y) {
    extern __shared__ float asmem[];
    float* Qs   = asmem;               // [64][ATP]  row-major (q-row, dim)
    float* Ks   = Qs + 64 * ATP;       // [64][ATP]  (key, dim)
    float* Vs   = Ks + 64 * ATP;       // [64][ATP]  (key, dim)
    float* Ps   = Vs + 64 * ATP;       // [64][ATP]  (q-row, key)  tf32
    float* mrow = Ps + 64 * ATP;       // [64]
    float* lrow = mrow + 64;
    float* cfac = lrow + 64;
    float* pmax = cfac + 64;           // [2][64]
    float* psum = pmax + 128;          // [2][64]

    int t    = threadIdx.x;
    int wid  = t >> 5;
    int lane = t & 31;
    int g    = lane >> 2;
    int tig  = lane & 3;
    int m0   = (wid & 3) * 16;        // M chunk (rows m0..m0+15)
    int n0   = (wid >> 2) * 32;       // N chunk (cols n0..n0+31)
    int nch  = wid >> 2;

    int q0 = blockIdx.x * 64;
    int h  = blockIdx.y;
    int b  = blockIdx.z;

    // load Q tile, convert to tf32
    for (int i = t; i < 64 * 16; i += 256) {
        int r = i >> 4, c4 = i & 15;
        float4 qv = *(const float4*)(q + ((size_t)(b * Tt + q0 + r)) * Dd + h * HD + c4 * 4);
        float* d = Qs + r * ATP + c4 * 4;
        d[0] = to_tf32(qv.x); d[1] = to_tf32(qv.y);
        d[2] = to_tf32(qv.z); d[3] = to_tf32(qv.w);
    }
    if (t < 64) { mrow[t] = -1e30f; lrow[t] = 0.f; }

    float oacc[4][4];                  // [n8][c0..c3]
#pragma unroll
    for (int in = 0; in < 4; in++)
#pragma unroll
        for (int c = 0; c < 4; c++) oacc[in][c] = 0.f;

    int ntiles = blockIdx.x + 1;
    __syncthreads();

    for (int jt = 0; jt < ntiles; jt++) {
        int s0 = jt * 64;
        bool diag = (jt == ntiles - 1);

        // load K,V tiles (tf32)
        for (int i = t; i < 64 * 16; i += 256) {
            int r = i >> 4, c4 = i & 15;
            size_t gb = ((size_t)(b * Tt + s0 + r)) * Dd + h * HD + c4 * 4;
            float4 kv = *(const float4*)(k + gb);
            float4 vv = *(const float4*)(v + gb);
            float* dk = Ks + r * ATP + c4 * 4;
            dk[0] = to_tf32(kv.x); dk[1] = to_tf32(kv.y);
            dk[2] = to_tf32(kv.z); dk[3] = to_tf32(kv.w);
            float* dv = Vs + r * ATP + c4 * 4;
            dv[0] = to_tf32(vv.x); dv[1] = to_tf32(vv.y);
            dv[2] = to_tf32(vv.z); dv[3] = to_tf32(vv.w);
        }
        __syncthreads();

        // ---- S = Q K^T: per-warp m16 x n32, K=64 (8 k-steps) ----
        float sacc[4][4];
#pragma unroll
        for (int in = 0; in < 4; in++)
#pragma unroll
            for (int c = 0; c < 4; c++) sacc[in][c] = 0.f;
#pragma unroll
        for (int k8 = 0; k8 < 8; k8++) {
            int kk = k8 * 8;
            unsigned a0 = __float_as_uint(Qs[(m0 + g    ) * ATP + kk + tig    ]);
            unsigned a1 = __float_as_uint(Qs[(m0 + g + 8) * ATP + kk + tig    ]);
            unsigned a2 = __float_as_uint(Qs[(m0 + g    ) * ATP + kk + tig + 4]);
            unsigned a3 = __float_as_uint(Qs[(m0 + g + 8) * ATP + kk + tig + 4]);
#pragma unroll
            for (int in = 0; in < 4; in++) {
                unsigned b0 = __float_as_uint(Ks[(n0 + in * 8 + g) * ATP + kk + tig    ]);
                unsigned b1 = __float_as_uint(Ks[(n0 + in * 8 + g) * ATP + kk + tig + 4]);
                asm volatile(
                    "mma.sync.aligned.m16n8k8.row.col.f32.tf32.tf32.f32 "
                    "{%0,%1,%2,%3},{%4,%5,%6,%7},{%8,%9},{%0,%1,%2,%3};"
                    : "+f"(sacc[in][0]), "+f"(sacc[in][1]),
                      "+f"(sacc[in][2]), "+f"(sacc[in][3])
                    : "r"(a0), "r"(a1), "r"(a2), "r"(a3), "r"(b0), "r"(b1));
            }
        }

        // scale + causal mask (mask only on diagonal tile)
        int r0 = m0 + g, r1 = m0 + g + 8;
#pragma unroll
        for (int in = 0; in < 4; in++) {
            int c0 = n0 + in * 8 + 2 * tig, c1 = c0 + 1;
            sacc[in][0] *= 0.125f; sacc[in][1] *= 0.125f;
            sacc[in][2] *= 0.125f; sacc[in][3] *= 0.125f;
            if (diag) {
                if (c0 > r0) sacc[in][0] = -1e30f;
                if (c1 > r0) sacc[in][1] = -1e30f;
                if (c0 > r1) sacc[in][2] = -1e30f;
                if (c1 > r1) sacc[in][3] = -1e30f;
            }
        }

        // per-warp row max over its 32 cols
        float rmax0 = -1e30f, rmax1 = -1e30f;
#pragma unroll
        for (int in = 0; in < 4; in++) {
            rmax0 = fmaxf(rmax0, fmaxf(sacc[in][0], sacc[in][1]));
            rmax1 = fmaxf(rmax1, fmaxf(sacc[in][2], sacc[in][3]));
        }
        rmax0 = fmaxf(rmax0, __shfl_xor_sync(0xffffffffu, rmax0, 1));
        rmax0 = fmaxf(rmax0, __shfl_xor_sync(0xffffffffu, rmax0, 2));
        rmax1 = fmaxf(rmax1, __shfl_xor_sync(0xffffffffu, rmax1, 1));
        rmax1 = fmaxf(rmax1, __shfl_xor_sync(0xffffffffu, rmax1, 2));
        if (tig == 0) {
            pmax[nch * 64 + r0] = rmax0;
            pmax[nch * 64 + r1] = rmax1;
        }
        __syncthreads();

        // combine: new max, correction
        if (t < 64) {
            float nm = fmaxf(mrow[t], fmaxf(pmax[t], pmax[64 + t]));
            cfac[t] = __expf(mrow[t] - nm);
            mrow[t] = nm;
        }
        __syncthreads();

        // exp, partial row-sums, store P (tf32) to smem
        float nm0 = mrow[r0], nm1 = mrow[r1];
        float rs0 = 0.f, rs1 = 0.f;
#pragma unroll
        for (int in = 0; in < 4; in++) {
            int c0 = n0 + in * 8 + 2 * tig;
            float p0 = __expf(sacc[in][0] - nm0);
            float p1 = __expf(sacc[in][1] - nm0);
            float p2 = __expf(sacc[in][2] - nm1);
            float p3 = __expf(sacc[in][3] - nm1);
            rs0 += p0 + p1; rs1 += p2 + p3;
            Ps[r0 * ATP + c0    ] = to_tf32(p0);
            Ps[r0 * ATP + c0 + 1] = to_tf32(p1);
            Ps[r1 * ATP + c0    ] = to_tf32(p2);
            Ps[r1 * ATP + c0 + 1] = to_tf32(p3);
        }
        rs0 += __shfl_xor_sync(0xffffffffu, rs0, 1);
        rs0 += __shfl_xor_sync(0xffffffffu, rs0, 2);
        rs1 += __shfl_xor_sync(0xffffffffu, rs1, 1);
        rs1 += __shfl_xor_sync(0xffffffffu, rs1, 2);
        if (tig == 0) {
            psum[nch * 64 + r0] = rs0;
            psum[nch * 64 + r1] = rs1;
        }
        __syncthreads();

        if (t < 64) lrow[t] = lrow[t] * cfac[t] + psum[t] + psum[64 + t];

        // rescale O accumulators
        float corr0 = cfac[r0], corr1 = cfac[r1];
#pragma unroll
        for (int in = 0; in < 4; in++) {
            oacc[in][0] *= corr0; oacc[in][1] *= corr0;
            oacc[in][2] *= corr1; oacc[in][3] *= corr1;
        }

        // ---- O += P V: per-warp m16 x n32, K=64 keys (8 k-steps) ----
#pragma unroll
        for (int k8 = 0; k8 < 8; k8++) {
            int kk = k8 * 8;
            unsigned a0 = __float_as_uint(Ps[(m0 + g    ) * ATP + kk + tig    ]);
            unsigned a1 = __float_as_uint(Ps[(m0 + g + 8) * ATP + kk + tig    ]);
            unsigned a2 = __float_as_uint(Ps[(m0 + g    ) * ATP + kk + tig + 4]);
            unsigned a3 = __float_as_uint(Ps[(m0 + g + 8) * ATP + kk + tig + 4]);
#pragma unroll
            for (int in = 0; in < 4; in++) {
                unsigned b0 = __float_as_uint(Vs[(kk + tig    ) * ATP + n0 + in * 8 + g]);
                unsigned b1 = __float_as_uint(Vs[(kk + tig + 4) * ATP + n0 + in * 8 + g]);
                asm volatile(
                    "mma.sync.aligned.m16n8k8.row.col.f32.tf32.tf32.f32 "
                    "{%0,%1,%2,%3},{%4,%5,%6,%7},{%8,%9},{%0,%1,%2,%3};"
                    : "+f"(oacc[in][0]), "+f"(oacc[in][1]),
                      "+f"(oacc[in][2]), "+f"(oacc[in][3])
                    : "r"(a0), "r"(a1), "r"(a2), "r"(a3), "r"(b0), "r"(b1));
            }
        }
        __syncthreads();   // protect Ks/Vs/Ps before next tile's fill
    }

    // normalize + store (float2: cols c0,c0+1 adjacent)
    int r0 = m0 + g, r1 = m0 + g + 8;
    float inv0 = 1.f / lrow[r0];
    float inv1 = 1.f / lrow[r1];
#pragma unroll
    for (int in = 0; in < 4; in++) {
        int c0 = n0 + in * 8 + 2 * tig;
        float2 o0, o1;
        o0.x = oacc[in][0] * inv0; o0.y = oacc[in][1] * inv0;
        o1.x = oacc[in][2] * inv1; o1.y = oacc[in][3] * inv1;
        *(float2*)(y + ((size_t)(b * Tt + q0 + r0)) * Dd + h * HD + c0) = o0;
        *(float2*)(y + ((size_t)(b * Tt + q0 + r1)) * Dd + h * HD + c0) = o1;
    }
}

// ---------------- residual + LayerNorm ----------------
__global__ __launch_bounds__(256)
void ln_res_kernel(const float* __restrict__ a, const float* __restrict__ b,
                   const float* __restrict__ g, const float* __restrict__ be,
                   float* __restrict__ out) {
    __shared__ float buf[Dd];
    __shared__ float red[256];
    int r = blockIdx.x;
    int t = threadIdx.x;
    const float* ar = a + (size_t)r * Dd;
    const float* br = b + (size_t)r * Dd;

    float s = 0.f;
    for (int c = t; c < Dd; c += 256) {
        float vv = ar[c] + br[c];
        buf[c] = vv;
        s += vv;
    }
    red[t] = s; __syncthreads();
    for (int o = 128; o > 0; o >>= 1) { if (t < o) red[t] += red[t + o]; __syncthreads(); }
    float mu = red[0] / (float)Dd;
    __syncthreads();

    float s2 = 0.f;
    for (int c = t; c < Dd; c += 256) {
        float d = buf[c] - mu;
        s2 += d * d;
    }
    red[t] = s2; __syncthreads();
    for (int o = 128; o > 0; o >>= 1) { if (t < o) red[t] += red[t + o]; __syncthreads(); }
    float rstd = rsqrtf(red[0] / (float)Dd + 1e-5f);

    float* orr = out + (size_t)r * Dd;
    for (int c = t; c < Dd; c += 256)
        orr[c] = (buf[c] - mu) * rstd * g[c] + be[c];
}

// ---------------- per-row cross-entropy ----------------
__global__ __launch_bounds__(256)
void rowloss_kernel(const float* __restrict__ logits, const int* __restrict__ tgt,
                    float* __restrict__ rl) {
    __shared__ float sm[256], sl[256];
    int r = blockIdx.x;
    int t = threadIdx.x;
    const float* lg = logits + (size_t)r * Vv;

    float m = -1e30f, l = 0.f;
    for (int c = t; c < Vv; c += 256) {
        float x = lg[c];
        if (x > m) { l = l * __expf(m - x) + 1.f; m = x; }
        else       { l += __expf(x - m); }
    }
    sm[t] = m; sl[t] = l; __syncthreads();
    for (int o = 128; o > 0; o >>= 1) {
        if (t < o) {
            float m1 = sm[t], m2 = sm[t + o];
            float M = fmaxf(m1, m2);
            sl[t] = sl[t] * __expf(m1 - M) + sl[t + o] * __expf(m2 - M);
            sm[t] = M;
        }
        __syncthreads();
    }
    if (t == 0)
        rl[r] = (sm[0] + logf(sl[0])) - lg[tgt[r]];
}

__global__ __launch_bounds__(256)
void meanloss_kernel(const float* __restrict__ rl, float* __restrict__ out) {
    __shared__ float red[256];
    int t = threadIdx.x;
    float s = 0.f;
    for (int i = t; i < BT; i += 256) s += rl[i];
    red[t] = s; __syncthreads();
    for (int o = 128; o > 0; o >>= 1) { if (t < o) red[t] += red[t + o]; __syncthreads(); }
    if (t == 0) out[0] = red[0] / (float)BT;
}

// ---------------- launch ----------------
extern "C" void kernel_launch(void* const* d_in, const int* in_sizes, int n_in,
                              void* d_out, int out_size) {
    const int*   idx    = (const int*)  d_in[0];
    const int*   tgt    = (const int*)  d_in[1];
    const float* tok    = (const float*)d_in[2];
    const float* pos    = (const float*)d_in[3];
    const float* Wq     = (const float*)d_in[4];
    const float* Wk     = (const float*)d_in[5];
    const float* Wv     = (const float*)d_in[6];
    const float* ln1g   = (const float*)d_in[7];
    const float* ln1b   = (const float*)d_in[8];
    const float* W1     = (const float*)d_in[9];
    const float* b1     = (const float*)d_in[10];
    const float* W2     = (const float*)d_in[11];
    const float* b2     = (const float*)d_in[12];
    const float* ln2g   = (const float*)d_in[13];
    const float* ln2b   = (const float*)d_in[14];
    const float* headw  = (const float*)d_in[15];
    const float* headb  = (const float*)d_in[16];
    float* out = (float*)d_out;

    float *x, *x2, *q, *k, *v, *y, *ff1, *rl, *wpad;
    cudaGetSymbolAddress((void**)&x,    g_x);
    cudaGetSymbolAddress((void**)&x2,   g_x2);
    cudaGetSymbolAddress((void**)&q,    g_q);
    cudaGetSymbolAddress((void**)&k,    g_k);
    cudaGetSymbolAddress((void**)&v,    g_v);
    cudaGetSymbolAddress((void**)&y,    g_y);
    cudaGetSymbolAddress((void**)&ff1,  g_ff1);
    cudaGetSymbolAddress((void**)&rl,   g_rl);
    cudaGetSymbolAddress((void**)&wpad, g_wpad);

    cudaFuncSetAttribute(attn_kernel,
                         cudaFuncAttributeMaxDynamicSharedMemorySize, ATTN_SMEM);

    embed_kernel<<<BT, 256>>>(idx, tok, pos, x);
    padw_kernel<<<Dd, 256>>>(headw, wpad);

    dim3 gQKV(18, BT / 128);
    dim3 gD(Dd / 128, BT / 128);             // 6 x 32
    dim3 gF(FF / 128, BT / 128);             // 24 x 32
    dim3 gV(VP / 128, BT / 128);             // 393 x 32

    for (int l = 0; l < Ll; l++) {
        const float* wq = Wq + (size_t)l * Dd * Dd;
        const float* wk = Wk + (size_t)l * Dd * Dd;
        const float* wv = Wv + (size_t)l * Dd * Dd;
        const float* w1 = W1 + (size_t)l * Dd * FF;
        const float* w2 = W2 + (size_t)l * FF * Dd;

        qkv_kernel<<<gQKV, 256>>>(x, wq, wk, wv, q, k, v);

        attn_kernel<<<dim3(Tt / 64, Hh, Bb), 256, ATTN_SMEM>>>(q, k, v, y);

        ln_res_kernel<<<BT, 256>>>(y, x, ln1g + l * Dd, ln1b + l * Dd, x2);

        tgemm_kernel<2><<<gF, 256>>>(x2, w1, b1 + (size_t)l * FF, ff1, FF, Dd, FF);
        tgemm_kernel<1><<<gD, 256>>>(ff1, w2, b2 + (size_t)l * Dd, y, Dd, FF, Dd);

        ln_res_kernel<<<BT, 256>>>(y, x2, ln2g + l * Dd, ln2b + l * Dd, x);
    }

    tgemm_kernel<1><<<gV, 256>>>(x, wpad, headb, out, Vv, Dd, VP);

    rowloss_kernel<<<BT, 256>>>(out, tgt, rl);
    meanloss_kernel<<<1, 256>>>(rl, out + (size_t)BT * Vv);
}